// round 16
// baseline (speedup 1.0000x reference)
#include <cuda_runtime.h>
#include <cub/cub.cuh>

// Problem constants
#define NB_   80000      // B*N nodes layer 0/1
#define BGR_  8          // graphs
#define NPG_  10000      // nodes per graph (layer 1)
#define EDG_  640000     // edges
#define CC_   128        // channels
#define FF_   64         // input features
#define KK1_  6000       // kept after pool1 (per graph)
#define NB1_  48000      // B*KK1
#define KK2_  3600       // kept after pool2 (per graph)
#define NB2_  28800      // B*KK2

// ---------------- static device scratch (no allocs allowed) ----------------
__device__ float g_bufA[NB_ * CC_];
__device__ float g_bufB[NB_ * CC_];
__device__ float g_bufC[NB_ * CC_];
__device__ float g_scores[NB_];
__device__ float g_srel[NB_];
__device__ float g_sroot[NB_];
__device__ float g_ssum[NB_];
__device__ unsigned long long g_key64[NB_];
__device__ unsigned long long g_key64B[NB_];
__device__ int   g_iota[NB_];
__device__ int   g_sidx[NB_];
__device__ int   g_newid[NB_];
__device__ int   g_esrc[EDG_];     // compacted remapped layer-2 edges
__device__ int   g_edst[EDG_];
__device__ int   g_ecount;
__device__ float g_out1[BGR_ * CC_];
__device__ float g_out2[BGR_ * CC_];
__device__ unsigned char g_cubtmp[1u << 24];  // 16 MB cub temp

// ---------------- XLA-GPU (MLIR math polynomial approximation) tanh -------
__device__ __forceinline__ float xla_tanh(float ax) {
    const float plus_clamp  = 7.99881172180175781f;
    const float minus_clamp = -7.99881172180175781f;
    const float tiny = 0.0004f;
    const float alpha_1  = 4.89352455891786e-03f;
    const float alpha_3  = 6.37261928875436e-04f;
    const float alpha_5  = 1.48572235717979e-05f;
    const float alpha_7  = 5.12229709037114e-08f;
    const float alpha_9  = -8.60467152213735e-11f;
    const float alpha_11 = 2.00018790482477e-13f;
    const float alpha_13 = -2.76076847742355e-16f;
    const float beta_0 = 4.89352518554385e-03f;
    const float beta_2 = 2.26843463243900e-03f;
    const float beta_4 = 1.18534705686654e-04f;
    const float beta_6 = 1.19825839466702e-06f;

    float x = fminf(fmaxf(ax, minus_clamp), plus_clamp);
    float x2 = x * x;
    float p = fmaf(x2, alpha_13, alpha_11);
    p = fmaf(x2, p, alpha_9);
    p = fmaf(x2, p, alpha_7);
    p = fmaf(x2, p, alpha_5);
    p = fmaf(x2, p, alpha_3);
    p = fmaf(x2, p, alpha_1);
    p = x * p;
    float q = fmaf(x2, beta_6, beta_4);
    q = fmaf(x2, q, beta_2);
    q = fmaf(x2, q, beta_0);
    float r = p / q;
    return (fabsf(ax) < tiny) ? ax : r;
}

// ---------------- GEMM (stage 0): [M x K] @ [K x 128] + bias + relu -------
template <int K, bool RELU, bool DUAL>
__global__ void __launch_bounds__(256) gemm_kernel(const float* __restrict__ A,
                                                   const float* __restrict__ W,
                                                   const float* __restrict__ bias,
                                                   float* __restrict__ out,
                                                   float* __restrict__ out2) {
    __shared__ float As[64][36];
    __shared__ float Bs[32][128];

    const int tid  = threadIdx.x;
    const int row0 = blockIdx.x * 64;
    const int warp = tid >> 5, lane = tid & 31;
    const int r0 = warp * 8;
    const int c0 = lane * 4;

    float acc[8][4];
#pragma unroll
    for (int i = 0; i < 8; i++)
#pragma unroll
        for (int j = 0; j < 4; j++) acc[i][j] = 0.f;

    for (int k0 = 0; k0 < K; k0 += 32) {
        {
            const int r  = tid >> 3;
            const int k4 = (tid & 7) * 4;
            float4 v0 = *(const float4*)(A + (size_t)(row0 + r) * K + k0 + k4);
            float4 v1 = *(const float4*)(A + (size_t)(row0 + r + 32) * K + k0 + k4);
            *(float4*)&As[r][k4]      = v0;
            *(float4*)&As[r + 32][k4] = v1;
        }
#pragma unroll
        for (int it = 0; it < 4; ++it) {
            const int f  = tid + it * 256;
            const int k  = f >> 5;
            const int c4 = (f & 31) * 4;
            *(float4*)&Bs[k][c4] = *(const float4*)(W + (size_t)(k0 + k) * 128 + c4);
        }
        __syncthreads();
#pragma unroll
        for (int kk = 0; kk < 32; ++kk) {
            const float4 b = *(const float4*)&Bs[kk][c0];
#pragma unroll
            for (int i = 0; i < 8; i++) {
                const float a = As[r0 + i][kk];
                acc[i][0] = fmaf(a, b.x, acc[i][0]);
                acc[i][1] = fmaf(a, b.y, acc[i][1]);
                acc[i][2] = fmaf(a, b.z, acc[i][2]);
                acc[i][3] = fmaf(a, b.w, acc[i][3]);
            }
        }
        __syncthreads();
    }

    const float4 bv = *(const float4*)(bias + c0);
#pragma unroll
    for (int i = 0; i < 8; i++) {
        float4 o;
        o.x = acc[i][0] + bv.x;
        o.y = acc[i][1] + bv.y;
        o.z = acc[i][2] + bv.z;
        o.w = acc[i][3] + bv.w;
        if (RELU) {
            o.x = fmaxf(o.x, 0.f); o.y = fmaxf(o.y, 0.f);
            o.z = fmaxf(o.z, 0.f); o.w = fmaxf(o.w, 0.f);
        }
        const size_t off = (size_t)(row0 + r0 + i) * 128 + c0;
        *(float4*)(out + off) = o;
        if (DUAL) *(float4*)(out2 + off) = o;
    }
}

// ---------------- fused GIN nn + score dots -------------------------------
__global__ void __launch_bounds__(256) gin_kernel(const float* __restrict__ A,
                                                  const float* __restrict__ Wa,
                                                  const float* __restrict__ ba,
                                                  const float* __restrict__ Wb,
                                                  const float* __restrict__ bb,
                                                  float* __restrict__ out,
                                                  const float* __restrict__ Wrel,
                                                  const float* __restrict__ Wroot,
                                                  float* __restrict__ srel,
                                                  float* __restrict__ sroot,
                                                  float* __restrict__ ssum) {
    extern __shared__ char smem[];
    float (*As)[36]  = (float(*)[36])smem;                    //  9216 B
    float (*Bs)[128] = (float(*)[128])(smem + 9216);          // 16384 B
    float (*T1)[132] = (float(*)[132])(smem + 9216 + 16384);  // 33792 B

    const int tid  = threadIdx.x;
    const int row0 = blockIdx.x * 64;
    const int warp = tid >> 5, lane = tid & 31;
    const int r0 = warp * 8;
    const int c0 = lane * 4;

    float acc[8][4];
#pragma unroll
    for (int i = 0; i < 8; i++)
#pragma unroll
        for (int j = 0; j < 4; j++) acc[i][j] = 0.f;

    // ---- phase 1: t1 = relu(A@Wa + ba)
    for (int k0 = 0; k0 < CC_; k0 += 32) {
        {
            const int r  = tid >> 3;
            const int k4 = (tid & 7) * 4;
            float4 v0 = *(const float4*)(A + (size_t)(row0 + r) * CC_ + k0 + k4);
            float4 v1 = *(const float4*)(A + (size_t)(row0 + r + 32) * CC_ + k0 + k4);
            *(float4*)&As[r][k4]      = v0;
            *(float4*)&As[r + 32][k4] = v1;
        }
#pragma unroll
        for (int it = 0; it < 4; ++it) {
            const int f  = tid + it * 256;
            const int k  = f >> 5;
            const int c4 = (f & 31) * 4;
            *(float4*)&Bs[k][c4] = *(const float4*)(Wa + (size_t)(k0 + k) * 128 + c4);
        }
        __syncthreads();
#pragma unroll
        for (int kk = 0; kk < 32; ++kk) {
            const float4 b = *(const float4*)&Bs[kk][c0];
#pragma unroll
            for (int i = 0; i < 8; i++) {
                const float a = As[r0 + i][kk];
                acc[i][0] = fmaf(a, b.x, acc[i][0]);
                acc[i][1] = fmaf(a, b.y, acc[i][1]);
                acc[i][2] = fmaf(a, b.z, acc[i][2]);
                acc[i][3] = fmaf(a, b.w, acc[i][3]);
            }
        }
        __syncthreads();
    }
    {
        const float4 bv = *(const float4*)(ba + c0);
#pragma unroll
        for (int i = 0; i < 8; i++) {
            float4 o;
            o.x = fmaxf(acc[i][0] + bv.x, 0.f);
            o.y = fmaxf(acc[i][1] + bv.y, 0.f);
            o.z = fmaxf(acc[i][2] + bv.z, 0.f);
            o.w = fmaxf(acc[i][3] + bv.w, 0.f);
            *(float4*)&T1[r0 + i][c0] = o;
        }
    }

    // ---- phase 2: out = t1 @ Wb + bb
#pragma unroll
    for (int i = 0; i < 8; i++)
#pragma unroll
        for (int j = 0; j < 4; j++) acc[i][j] = 0.f;

    for (int k0 = 0; k0 < CC_; k0 += 32) {
#pragma unroll
        for (int it = 0; it < 4; ++it) {
            const int f  = tid + it * 256;
            const int k  = f >> 5;
            const int c4 = (f & 31) * 4;
            *(float4*)&Bs[k][c4] = *(const float4*)(Wb + (size_t)(k0 + k) * 128 + c4);
        }
        __syncthreads();   // also orders T1 writes before T1 reads (k0 == 0)
#pragma unroll
        for (int kk = 0; kk < 32; ++kk) {
            const float4 b = *(const float4*)&Bs[kk][c0];
#pragma unroll
            for (int i = 0; i < 8; i++) {
                const float a = T1[r0 + i][k0 + kk];
                acc[i][0] = fmaf(a, b.x, acc[i][0]);
                acc[i][1] = fmaf(a, b.y, acc[i][1]);
                acc[i][2] = fmaf(a, b.z, acc[i][2]);
                acc[i][3] = fmaf(a, b.w, acc[i][3]);
            }
        }
        __syncthreads();
    }
    {
        const float4 bv = *(const float4*)(bb + c0);
        const float4 wr = *(const float4*)(Wrel + c0);
        const float4 wt = *(const float4*)(Wroot + c0);
#pragma unroll
        for (int i = 0; i < 8; i++) {
            float4 o;
            o.x = acc[i][0] + bv.x;
            o.y = acc[i][1] + bv.y;
            o.z = acc[i][2] + bv.z;
            o.w = acc[i][3] + bv.w;
            *(float4*)(out + (size_t)(row0 + r0 + i) * 128 + c0) = o;
            float t1 = o.x * wr.x + o.y * wr.y + o.z * wr.z + o.w * wr.w;
            float t2 = o.x * wt.x + o.y * wt.y + o.z * wt.z + o.w * wt.w;
#pragma unroll
            for (int of = 16; of > 0; of >>= 1) {
                t1 += __shfl_xor_sync(0xffffffffu, t1, of);
                t2 += __shfl_xor_sync(0xffffffffu, t2, of);
            }
            if (lane == 0) {
                const int row = row0 + r0 + i;
                srel[row] = t1;
                sroot[row] = t2;
                ssum[row] = 0.f;
            }
        }
    }
}
#define GIN_SMEM (9216 + 16384 + 33792)

// ---------------- edge vector scatter-add (8 edges / warp, MLP=8) ---------
// cnt: optional device-side edge count (compacted list); else nE.
#define SCAT_EPW 8
__global__ void scatter_kernel(const float* __restrict__ x, const int* __restrict__ src,
                               const int* __restrict__ dst,
                               const int* __restrict__ cnt,
                               float* __restrict__ agg, int nE) {
    if (cnt) nE = *cnt;
    const int w = (blockIdx.x * blockDim.x + threadIdx.x) >> 5;
    const int lane = threadIdx.x & 31;
    const int e0 = w * SCAT_EPW;
    if (e0 >= nE) return;
    float4 v[SCAT_EPW];
    int d[SCAT_EPW];
    bool ok[SCAT_EPW];
#pragma unroll
    for (int i = 0; i < SCAT_EPW; i++) {
        const int e = e0 + i;
        ok[i] = (e < nE);
        if (ok[i]) {
            const int s = src[e];
            d[i] = dst[e];
            v[i] = *(const float4*)(x + (size_t)s * CC_ + lane * 4);
        }
    }
#pragma unroll
    for (int i = 0; i < SCAT_EPW; i++)
        if (ok[i])
            atomicAdd((float4*)(agg + (size_t)d[i] * CC_ + lane * 4), v[i]);
}

// ---------------- scalar edge scatter-add for scores (4 edges / thread) ---
__global__ void scatter_scalar_kernel(const float* __restrict__ srel,
                                      const int* __restrict__ src,
                                      const int* __restrict__ dst,
                                      const int* __restrict__ cnt,
                                      float* __restrict__ ssum, int nE) {
    if (cnt) nE = *cnt;
    const int t = blockIdx.x * blockDim.x + threadIdx.x;
    const int e0 = t * 4;
    if (e0 >= nE) return;
#pragma unroll
    for (int i = 0; i < 4; i++) {
        const int e = e0 + i;
        if (e < nE) {
            const int s = src[e];
            const int d = dst[e];
            atomicAdd(&ssum[d], srel[s]);
        }
    }
}

// ---------------- edge compaction for the pooled (layer-2) graph ----------
// Keeps edges with both endpoints surviving pool-1, already remapped.
// Output order is arbitrary (scatter accumulation is order-free).
__global__ void compact_kernel(const int* __restrict__ src, const int* __restrict__ dst,
                               const int* __restrict__ newid,
                               int* __restrict__ esrc, int* __restrict__ edst,
                               int* __restrict__ ecount) {
    const int e = blockIdx.x * blockDim.x + threadIdx.x;
    if (e >= EDG_) return;
    const int s = newid[src[e]];
    const int d = newid[dst[e]];
    const bool ok = (s >= 0) && (d >= 0);
    const unsigned int ballot = __ballot_sync(0xffffffffu, ok);
    const int lane = threadIdx.x & 31;
    int base = 0;
    if (lane == 0 && ballot)
        base = atomicAdd(ecount, __popc(ballot));
    base = __shfl_sync(0xffffffffu, base, 0);
    if (ok) {
        const int pos = base + __popc(ballot & ((1u << lane) - 1u));
        esrc[pos] = s;
        edst[pos] = d;
    }
}

// ---------------- score finalize + composite sort key + inits -------------
__global__ void score_fin_kernel(const float* __restrict__ ssum,
                                 const float* __restrict__ sroot,
                                 const float* __restrict__ brel,
                                 float* __restrict__ scores,
                                 unsigned long long* __restrict__ key64,
                                 int* __restrict__ iota,
                                 int* __restrict__ newid_init,
                                 int* __restrict__ ecount_zero,
                                 float* __restrict__ ozero,
                                 int npg, int n) {
    const int node = blockIdx.x * blockDim.x + threadIdx.x;
    if (node >= n) return;
    const float sc = xla_tanh((ssum[node] + brel[0]) + sroot[node]);
    scores[node] = sc;
    unsigned int u = __float_as_uint(sc);
    unsigned int e = (u & 0x80000000u) ? ~u : (u | 0x80000000u); // ascending encode
    unsigned int kd = ~e;                                         // descending
    const unsigned int g = (unsigned int)(node / npg);
    key64[node] = ((unsigned long long)g << 32) | (unsigned long long)kd;
    iota[node] = node;
    if (newid_init) newid_init[node] = -1;
    if (ecount_zero && node == 0) *ecount_zero = 0;
    if (ozero && node < BGR_ * CC_) ozero[node] = 0.f;
}

// ---------------- selection/gather after sort (1 warp / kept node) -------
__global__ void select_kernel(const float* __restrict__ scores, const int* __restrict__ sidx,
                              const float* __restrict__ xin, float* __restrict__ xout,
                              float* __restrict__ xout2,
                              int* __restrict__ newid, int npg, int k) {
    const int j = blockIdx.x * 8 + (threadIdx.x >> 5);
    if (j >= BGR_ * k) return;
    const int g = j / k, jj = j - g * k;
    const int srcpos = g * npg + jj;
    const int orig = sidx[srcpos];
    const float val = scores[orig];
    const int lane = threadIdx.x & 31;
    float4 v = *(const float4*)(xin + (size_t)orig * CC_ + lane * 4);
    v.x *= val; v.y *= val; v.z *= val; v.w *= val;
    const size_t off = (size_t)j * CC_ + lane * 4;
    *(float4*)(xout + off) = v;
    if (xout2) *(float4*)(xout2 + off) = v;
    if (lane == 0) newid[orig] = j;
}

// ---------------- per-graph mean pooling: parallel partial sums ----------
#define MEAN_BPG 16
__global__ void mean_part_kernel(const float* __restrict__ x, float* __restrict__ out, int k) {
    const int b = blockIdx.x / MEAN_BPG;
    const int chunk = blockIdx.x % MEAN_BPG;
    const int rows = (k + MEAN_BPG - 1) / MEAN_BPG;
    const int r0 = chunk * rows;
    const int r1 = (r0 + rows < k) ? (r0 + rows) : k;
    const int col = threadIdx.x;  // 0..127
    float s = 0.f;
    for (int r = r0; r < r1; ++r)
        s += x[((size_t)b * k + r) * CC_ + col];
    atomicAdd(&out[b * CC_ + col], s);
}

// ---------------- final MLP head (single block) ----------------
__global__ void head_kernel(const float* __restrict__ out1, const float* __restrict__ out2,
                            const float* __restrict__ Wg, const float* __restrict__ bg,
                            const float* __restrict__ Wr1, const float* __restrict__ br1,
                            const float* __restrict__ gg1, const float* __restrict__ be1,
                            const float* __restrict__ Wr2, const float* __restrict__ br2,
                            const float* __restrict__ gg2, const float* __restrict__ be2,
                            const float* __restrict__ Wout, float* __restrict__ out) {
    __shared__ float cat[8][256];
    __shared__ float gmat[8][128];
    __shared__ float r1[8][64];
    __shared__ float r2[8][32];
    const int tid = threadIdx.x;  // 256 threads
    for (int i = tid; i < 8 * 128; i += 256) {
        const int b = i >> 7, c = i & 127;
        cat[b][c]       = out1[i] / (float)KK1_;
        cat[b][c + 128] = out2[i] / (float)KK2_;
    }
    __syncthreads();
    const float inv = 1.0f / sqrtf(1.0f + 1e-5f);
    if (tid < 128) {
        for (int b = 0; b < 8; b++) {
            float s = 0.f;
            for (int k = 0; k < 256; k++) s = fmaf(cat[b][k], Wg[k * 128 + tid], s);
            gmat[b][tid] = s + bg[tid];
        }
    }
    __syncthreads();
    if (tid < 64) {
        for (int b = 0; b < 8; b++) {
            float s = 0.f;
            for (int k = 0; k < 128; k++) s = fmaf(gmat[b][k], Wr1[k * 64 + tid], s);
            s = (s + br1[tid]) * inv * gg1[tid] + be1[tid];
            r1[b][tid] = fmaxf(s, 0.f);
        }
    }
    __syncthreads();
    if (tid < 32) {
        for (int b = 0; b < 8; b++) {
            float s = 0.f;
            for (int k = 0; k < 64; k++) s = fmaf(r1[b][k], Wr2[k * 32 + tid], s);
            s = (s + br2[tid]) * inv * gg2[tid] + be2[tid];
            r2[b][tid] = fmaxf(s, 0.f);
        }
    }
    __syncthreads();
    if (tid < 32) {
        const int b = tid >> 2, j = tid & 3;
        float s = 0.f;
        for (int k = 0; k < 32; k++) s = fmaf(r2[b][k], Wout[k * 4 + j], s);
        out[b * 4 + j] = s;
    }
}

// ---------------- host orchestration ----------------
extern "C" void kernel_launch(void* const* d_in, const int* in_sizes, int n_in,
                              void* d_out, int out_size) {
    const float* x    = (const float*)d_in[0];
    const int*   ei   = (const int*)d_in[1];
    const int*   src  = ei;
    const int*   dst  = ei + EDG_;
    const float* W0   = (const float*)d_in[3];
    const float* b0   = (const float*)d_in[4];
    const float* W1a  = (const float*)d_in[5];
    const float* b1a  = (const float*)d_in[6];
    const float* W1b  = (const float*)d_in[7];
    const float* b1b  = (const float*)d_in[8];
    const float* Wrel1  = (const float*)d_in[9];
    const float* brel1  = (const float*)d_in[10];
    const float* Wroot1 = (const float*)d_in[11];
    const float* W2a  = (const float*)d_in[12];
    const float* b2a  = (const float*)d_in[13];
    const float* W2b  = (const float*)d_in[14];
    const float* b2b  = (const float*)d_in[15];
    const float* Wrel2  = (const float*)d_in[16];
    const float* brel2  = (const float*)d_in[17];
    const float* Wroot2 = (const float*)d_in[18];
    const float* Wg   = (const float*)d_in[19];
    const float* bg   = (const float*)d_in[20];
    const float* Wr1  = (const float*)d_in[21];
    const float* br1  = (const float*)d_in[22];
    const float* gg1  = (const float*)d_in[23];
    const float* be1  = (const float*)d_in[24];
    const float* Wr2  = (const float*)d_in[25];
    const float* br2  = (const float*)d_in[26];
    const float* gg2  = (const float*)d_in[27];
    const float* be2  = (const float*)d_in[28];
    const float* Wout = (const float*)d_in[29];

    float *bufA, *bufB, *bufC, *scores, *srel, *sroot, *ssum, *o1, *o2;
    unsigned long long *key64, *key64B;
    int *iota, *sidx, *newid, *esrc, *edst, *ecount;
    unsigned char *cubtmp;
    cudaGetSymbolAddress((void**)&bufA, g_bufA);
    cudaGetSymbolAddress((void**)&bufB, g_bufB);
    cudaGetSymbolAddress((void**)&bufC, g_bufC);
    cudaGetSymbolAddress((void**)&scores, g_scores);
    cudaGetSymbolAddress((void**)&srel, g_srel);
    cudaGetSymbolAddress((void**)&sroot, g_sroot);
    cudaGetSymbolAddress((void**)&ssum, g_ssum);
    cudaGetSymbolAddress((void**)&key64, g_key64);
    cudaGetSymbolAddress((void**)&key64B, g_key64B);
    cudaGetSymbolAddress((void**)&iota, g_iota);
    cudaGetSymbolAddress((void**)&sidx, g_sidx);
    cudaGetSymbolAddress((void**)&newid, g_newid);
    cudaGetSymbolAddress((void**)&esrc, g_esrc);
    cudaGetSymbolAddress((void**)&edst, g_edst);
    cudaGetSymbolAddress((void**)&ecount, g_ecount);
    cudaGetSymbolAddress((void**)&o1, g_out1);
    cudaGetSymbolAddress((void**)&o2, g_out2);
    cudaGetSymbolAddress((void**)&cubtmp, g_cubtmp);

    cudaFuncSetAttribute(gin_kernel, cudaFuncAttributeMaxDynamicSharedMemorySize, GIN_SMEM);

    const int scat_blocks = (EDG_ + SCAT_EPW * 8 - 1) / (SCAT_EPW * 8);

    // ---- stage 0: h0 = relu(x @ W0 + b0) -> bufA AND bufB (scatter base)
    gemm_kernel<FF_, true, true><<<NB_ / 64, 256>>>(x, W0, b0, bufA, bufB);

    // ---- GIN layer 1: bufB += segsum(h0) ; h1 = gin(bufB), + score dots
    scatter_kernel<<<scat_blocks, 256>>>(bufA, src, dst, nullptr, bufB, EDG_);
    gin_kernel<<<NB_ / 64, 256, GIN_SMEM>>>(bufB, W1a, b1a, W1b, b1b, bufB,
                                            Wrel1, Wroot1, srel, sroot, ssum);  // h1 = bufB

    // ---- SAGPool 1
    scatter_scalar_kernel<<<(EDG_ / 4 + 255) / 256, 256>>>(srel, src, dst, nullptr, ssum, EDG_);
    score_fin_kernel<<<(NB_ + 255) / 256, 256>>>(ssum, sroot, brel1, scores, key64, iota,
                                                 newid, ecount, o1, NPG_, NB_);
    {
        size_t tmp = 0;
        cub::DeviceRadixSort::SortPairs(nullptr, tmp, key64, key64B, iota, sidx, NB_, 0, 35);
        if (tmp > sizeof(g_cubtmp)) tmp = sizeof(g_cubtmp);
        cub::DeviceRadixSort::SortPairs((void*)cubtmp, tmp, key64, key64B, iota, sidx, NB_, 0, 35);
    }
    // h2 -> bufC AND bufA (layer-2 scatter base)
    select_kernel<<<NB1_ / 8, 256>>>(scores, sidx, bufB, bufC, bufA, newid, NPG_, KK1_);
    // compact surviving edges (remapped) for layer 2
    compact_kernel<<<EDG_ / 256, 256>>>(src, dst, newid, esrc, edst, ecount);
    mean_part_kernel<<<BGR_ * MEAN_BPG, 128>>>(bufC, o1, KK1_);

    // ---- GIN layer 2: bufA += segsum(h2, compacted edges) ; h3 = gin(bufA)
    scatter_kernel<<<scat_blocks, 256>>>(bufC, esrc, edst, ecount, bufA, EDG_);
    gin_kernel<<<NB1_ / 64, 256, GIN_SMEM>>>(bufA, W2a, b2a, W2b, b2b, bufC,
                                             Wrel2, Wroot2, srel, sroot, ssum);  // h3 = bufC

    // ---- SAGPool 2
    scatter_scalar_kernel<<<(EDG_ / 4 + 255) / 256, 256>>>(srel, esrc, edst, ecount, ssum, EDG_);
    score_fin_kernel<<<(NB1_ + 255) / 256, 256>>>(ssum, sroot, brel2, scores, key64, iota,
                                                  nullptr, nullptr, o2, KK1_, NB1_);
    {
        size_t tmp = 0;
        cub::DeviceRadixSort::SortPairs(nullptr, tmp, key64, key64B, iota, sidx, NB1_, 0, 35);
        if (tmp > sizeof(g_cubtmp)) tmp = sizeof(g_cubtmp);
        cub::DeviceRadixSort::SortPairs((void*)cubtmp, tmp, key64, key64B, iota, sidx, NB1_, 0, 35);
    }
    select_kernel<<<NB2_ / 8, 256>>>(scores, sidx, bufC, bufB, nullptr, newid, KK1_, KK2_);
    mean_part_kernel<<<BGR_ * MEAN_BPG, 128>>>(bufB, o2, KK2_);

    // ---- head
    head_kernel<<<1, 256>>>(o1, o2, Wg, bg, Wr1, br1, gg1, be1,
                            Wr2, br2, gg2, be2, Wout, (float*)d_out);
}

// round 17
// speedup vs baseline: 1.5084x; 1.5084x over previous
#include <cuda_runtime.h>
#include <cub/cub.cuh>

// Problem constants
#define NB_   80000      // B*N nodes layer 0/1
#define BGR_  8          // graphs
#define NPG_  10000      // nodes per graph (layer 1)
#define EDG_  640000     // edges
#define CC_   128        // channels
#define FF_   64         // input features
#define KK1_  6000       // kept after pool1 (per graph)
#define NB1_  48000      // B*KK1
#define KK2_  3600       // kept after pool2 (per graph)
#define NB2_  28800      // B*KK2

// ---------------- static device scratch (no allocs allowed) ----------------
__device__ float g_bufA[NB_ * CC_];
__device__ float g_bufB[NB_ * CC_];
__device__ float g_bufC[NB_ * CC_];
__device__ float g_scores[NB_];
__device__ float g_srel[NB_];
__device__ float g_sroot[NB_];
__device__ float g_ssum[NB_];
__device__ unsigned long long g_key64[NB_];
__device__ unsigned long long g_key64B[NB_];
__device__ int   g_iota[NB_];
__device__ int   g_sidx[NB_];
__device__ int   g_newid[NB_];
__device__ float g_out1[BGR_ * CC_];
__device__ float g_out2[BGR_ * CC_];
__device__ unsigned char g_cubtmp[1u << 24];  // 16 MB cub temp

// ---------------- XLA-GPU (MLIR math polynomial approximation) tanh -------
__device__ __forceinline__ float xla_tanh(float ax) {
    const float plus_clamp  = 7.99881172180175781f;
    const float minus_clamp = -7.99881172180175781f;
    const float tiny = 0.0004f;
    const float alpha_1  = 4.89352455891786e-03f;
    const float alpha_3  = 6.37261928875436e-04f;
    const float alpha_5  = 1.48572235717979e-05f;
    const float alpha_7  = 5.12229709037114e-08f;
    const float alpha_9  = -8.60467152213735e-11f;
    const float alpha_11 = 2.00018790482477e-13f;
    const float alpha_13 = -2.76076847742355e-16f;
    const float beta_0 = 4.89352518554385e-03f;
    const float beta_2 = 2.26843463243900e-03f;
    const float beta_4 = 1.18534705686654e-04f;
    const float beta_6 = 1.19825839466702e-06f;

    float x = fminf(fmaxf(ax, minus_clamp), plus_clamp);
    float x2 = x * x;
    float p = fmaf(x2, alpha_13, alpha_11);
    p = fmaf(x2, p, alpha_9);
    p = fmaf(x2, p, alpha_7);
    p = fmaf(x2, p, alpha_5);
    p = fmaf(x2, p, alpha_3);
    p = fmaf(x2, p, alpha_1);
    p = x * p;
    float q = fmaf(x2, beta_6, beta_4);
    q = fmaf(x2, q, beta_2);
    q = fmaf(x2, q, beta_0);
    float r = p / q;
    return (fabsf(ax) < tiny) ? ax : r;
}

// ---------------- GEMM (stage 0): [M x K] @ [K x 128] + bias + relu -------
template <int K, bool RELU, bool DUAL>
__global__ void __launch_bounds__(256) gemm_kernel(const float* __restrict__ A,
                                                   const float* __restrict__ W,
                                                   const float* __restrict__ bias,
                                                   float* __restrict__ out,
                                                   float* __restrict__ out2) {
    __shared__ float As[64][36];
    __shared__ float Bs[32][128];

    const int tid  = threadIdx.x;
    const int row0 = blockIdx.x * 64;
    const int warp = tid >> 5, lane = tid & 31;
    const int r0 = warp * 8;
    const int c0 = lane * 4;

    float acc[8][4];
#pragma unroll
    for (int i = 0; i < 8; i++)
#pragma unroll
        for (int j = 0; j < 4; j++) acc[i][j] = 0.f;

    for (int k0 = 0; k0 < K; k0 += 32) {
        {
            const int r  = tid >> 3;
            const int k4 = (tid & 7) * 4;
            float4 v0 = *(const float4*)(A + (size_t)(row0 + r) * K + k0 + k4);
            float4 v1 = *(const float4*)(A + (size_t)(row0 + r + 32) * K + k0 + k4);
            *(float4*)&As[r][k4]      = v0;
            *(float4*)&As[r + 32][k4] = v1;
        }
#pragma unroll
        for (int it = 0; it < 4; ++it) {
            const int f  = tid + it * 256;
            const int k  = f >> 5;
            const int c4 = (f & 31) * 4;
            *(float4*)&Bs[k][c4] = *(const float4*)(W + (size_t)(k0 + k) * 128 + c4);
        }
        __syncthreads();
#pragma unroll
        for (int kk = 0; kk < 32; ++kk) {
            const float4 b = *(const float4*)&Bs[kk][c0];
#pragma unroll
            for (int i = 0; i < 8; i++) {
                const float a = As[r0 + i][kk];
                acc[i][0] = fmaf(a, b.x, acc[i][0]);
                acc[i][1] = fmaf(a, b.y, acc[i][1]);
                acc[i][2] = fmaf(a, b.z, acc[i][2]);
                acc[i][3] = fmaf(a, b.w, acc[i][3]);
            }
        }
        __syncthreads();
    }

    const float4 bv = *(const float4*)(bias + c0);
#pragma unroll
    for (int i = 0; i < 8; i++) {
        float4 o;
        o.x = acc[i][0] + bv.x;
        o.y = acc[i][1] + bv.y;
        o.z = acc[i][2] + bv.z;
        o.w = acc[i][3] + bv.w;
        if (RELU) {
            o.x = fmaxf(o.x, 0.f); o.y = fmaxf(o.y, 0.f);
            o.z = fmaxf(o.z, 0.f); o.w = fmaxf(o.w, 0.f);
        }
        const size_t off = (size_t)(row0 + r0 + i) * 128 + c0;
        *(float4*)(out + off) = o;
        if (DUAL) *(float4*)(out2 + off) = o;
    }
}

// ---------------- fused GIN nn + score dots -------------------------------
// out = relu(A@Wa+ba) @ Wb + bb, then per-row srel = h.Wrel, sroot = h.Wroot
// (float4 lane dot + butterfly reduce), lane0 writes srel/sroot, zeroes ssum.
__global__ void __launch_bounds__(256) gin_kernel(const float* __restrict__ A,
                                                  const float* __restrict__ Wa,
                                                  const float* __restrict__ ba,
                                                  const float* __restrict__ Wb,
                                                  const float* __restrict__ bb,
                                                  float* __restrict__ out,
                                                  const float* __restrict__ Wrel,
                                                  const float* __restrict__ Wroot,
                                                  float* __restrict__ srel,
                                                  float* __restrict__ sroot,
                                                  float* __restrict__ ssum) {
    extern __shared__ char smem[];
    float (*As)[36]  = (float(*)[36])smem;                    //  9216 B
    float (*Bs)[128] = (float(*)[128])(smem + 9216);          // 16384 B
    float (*T1)[132] = (float(*)[132])(smem + 9216 + 16384);  // 33792 B

    const int tid  = threadIdx.x;
    const int row0 = blockIdx.x * 64;
    const int warp = tid >> 5, lane = tid & 31;
    const int r0 = warp * 8;
    const int c0 = lane * 4;

    float acc[8][4];
#pragma unroll
    for (int i = 0; i < 8; i++)
#pragma unroll
        for (int j = 0; j < 4; j++) acc[i][j] = 0.f;

    // ---- phase 1: t1 = relu(A@Wa + ba)
    for (int k0 = 0; k0 < CC_; k0 += 32) {
        {
            const int r  = tid >> 3;
            const int k4 = (tid & 7) * 4;
            float4 v0 = *(const float4*)(A + (size_t)(row0 + r) * CC_ + k0 + k4);
            float4 v1 = *(const float4*)(A + (size_t)(row0 + r + 32) * CC_ + k0 + k4);
            *(float4*)&As[r][k4]      = v0;
            *(float4*)&As[r + 32][k4] = v1;
        }
#pragma unroll
        for (int it = 0; it < 4; ++it) {
            const int f  = tid + it * 256;
            const int k  = f >> 5;
            const int c4 = (f & 31) * 4;
            *(float4*)&Bs[k][c4] = *(const float4*)(Wa + (size_t)(k0 + k) * 128 + c4);
        }
        __syncthreads();
#pragma unroll
        for (int kk = 0; kk < 32; ++kk) {
            const float4 b = *(const float4*)&Bs[kk][c0];
#pragma unroll
            for (int i = 0; i < 8; i++) {
                const float a = As[r0 + i][kk];
                acc[i][0] = fmaf(a, b.x, acc[i][0]);
                acc[i][1] = fmaf(a, b.y, acc[i][1]);
                acc[i][2] = fmaf(a, b.z, acc[i][2]);
                acc[i][3] = fmaf(a, b.w, acc[i][3]);
            }
        }
        __syncthreads();
    }
    {
        const float4 bv = *(const float4*)(ba + c0);
#pragma unroll
        for (int i = 0; i < 8; i++) {
            float4 o;
            o.x = fmaxf(acc[i][0] + bv.x, 0.f);
            o.y = fmaxf(acc[i][1] + bv.y, 0.f);
            o.z = fmaxf(acc[i][2] + bv.z, 0.f);
            o.w = fmaxf(acc[i][3] + bv.w, 0.f);
            *(float4*)&T1[r0 + i][c0] = o;
        }
    }

    // ---- phase 2: out = t1 @ Wb + bb
#pragma unroll
    for (int i = 0; i < 8; i++)
#pragma unroll
        for (int j = 0; j < 4; j++) acc[i][j] = 0.f;

    for (int k0 = 0; k0 < CC_; k0 += 32) {
#pragma unroll
        for (int it = 0; it < 4; ++it) {
            const int f  = tid + it * 256;
            const int k  = f >> 5;
            const int c4 = (f & 31) * 4;
            *(float4*)&Bs[k][c4] = *(const float4*)(Wb + (size_t)(k0 + k) * 128 + c4);
        }
        __syncthreads();   // also orders T1 writes before T1 reads (k0 == 0)
#pragma unroll
        for (int kk = 0; kk < 32; ++kk) {
            const float4 b = *(const float4*)&Bs[kk][c0];
#pragma unroll
            for (int i = 0; i < 8; i++) {
                const float a = T1[r0 + i][k0 + kk];
                acc[i][0] = fmaf(a, b.x, acc[i][0]);
                acc[i][1] = fmaf(a, b.y, acc[i][1]);
                acc[i][2] = fmaf(a, b.z, acc[i][2]);
                acc[i][3] = fmaf(a, b.w, acc[i][3]);
            }
        }
        __syncthreads();
    }
    {
        const float4 bv = *(const float4*)(bb + c0);
        const float4 wr = *(const float4*)(Wrel + c0);
        const float4 wt = *(const float4*)(Wroot + c0);
#pragma unroll
        for (int i = 0; i < 8; i++) {
            float4 o;
            o.x = acc[i][0] + bv.x;
            o.y = acc[i][1] + bv.y;
            o.z = acc[i][2] + bv.z;
            o.w = acc[i][3] + bv.w;
            *(float4*)(out + (size_t)(row0 + r0 + i) * 128 + c0) = o;
            // score dots (same structure as R11 score_pre)
            float t1 = o.x * wr.x + o.y * wr.y + o.z * wr.z + o.w * wr.w;
            float t2 = o.x * wt.x + o.y * wt.y + o.z * wt.z + o.w * wt.w;
#pragma unroll
            for (int of = 16; of > 0; of >>= 1) {
                t1 += __shfl_xor_sync(0xffffffffu, t1, of);
                t2 += __shfl_xor_sync(0xffffffffu, t2, of);
            }
            if (lane == 0) {
                const int row = row0 + r0 + i;
                srel[row] = t1;
                sroot[row] = t2;
                ssum[row] = 0.f;
            }
        }
    }
}
#define GIN_SMEM (9216 + 16384 + 33792)

// ---------------- edge vector scatter-add (8 edges / warp, MLP=8) ---------
// If newid != nullptr, edge endpoints are remapped through it; an edge is
// valid iff both remapped ids are >= 0 (layer-2 pooled graph).
#define SCAT_EPW 8
__global__ void scatter_kernel(const float* __restrict__ x, const int* __restrict__ src,
                               const int* __restrict__ dst,
                               const int* __restrict__ newid,
                               float* __restrict__ agg, int nE) {
    const int w = (blockIdx.x * blockDim.x + threadIdx.x) >> 5;
    const int lane = threadIdx.x & 31;
    const int e0 = w * SCAT_EPW;
    if (e0 >= nE) return;
    float4 v[SCAT_EPW];
    int d[SCAT_EPW];
    bool ok[SCAT_EPW];
#pragma unroll
    for (int i = 0; i < SCAT_EPW; i++) {
        const int e = e0 + i;
        ok[i] = (e < nE);
        if (ok[i]) {
            int s = src[e];
            d[i] = dst[e];
            if (newid) {
                s = newid[s];
                d[i] = newid[d[i]];
                ok[i] = (s >= 0) && (d[i] >= 0);
            }
            if (ok[i]) v[i] = *(const float4*)(x + (size_t)s * CC_ + lane * 4);
        }
    }
#pragma unroll
    for (int i = 0; i < SCAT_EPW; i++)
        if (ok[i])
            atomicAdd((float4*)(agg + (size_t)d[i] * CC_ + lane * 4), v[i]);
}

// ---------------- scalar edge scatter-add for scores (4 edges / thread) ---
__global__ void scatter_scalar_kernel(const float* __restrict__ srel,
                                      const int* __restrict__ src,
                                      const int* __restrict__ dst,
                                      const int* __restrict__ newid,
                                      float* __restrict__ ssum, int nE) {
    const int t = blockIdx.x * blockDim.x + threadIdx.x;
    const int e0 = t * 4;
    if (e0 >= nE) return;
    int4 s4 = *(const int4*)(src + e0);
    int4 d4 = *(const int4*)(dst + e0);
    bool m0 = true, m1 = true, m2 = true, m3 = true;
    if (newid) {
        s4.x = newid[s4.x]; d4.x = newid[d4.x]; m0 = (s4.x >= 0) && (d4.x >= 0);
        s4.y = newid[s4.y]; d4.y = newid[d4.y]; m1 = (s4.y >= 0) && (d4.y >= 0);
        s4.z = newid[s4.z]; d4.z = newid[d4.z]; m2 = (s4.z >= 0) && (d4.z >= 0);
        s4.w = newid[s4.w]; d4.w = newid[d4.w]; m3 = (s4.w >= 0) && (d4.w >= 0);
    }
    float a0 = 0.f, a1 = 0.f, a2 = 0.f, a3 = 0.f;
    if (m0) a0 = srel[s4.x];
    if (m1) a1 = srel[s4.y];
    if (m2) a2 = srel[s4.z];
    if (m3) a3 = srel[s4.w];
    if (m0) atomicAdd(&ssum[d4.x], a0);
    if (m1) atomicAdd(&ssum[d4.y], a1);
    if (m2) atomicAdd(&ssum[d4.z], a2);
    if (m3) atomicAdd(&ssum[d4.w], a3);
}

// ---------------- score finalize + composite sort key + inits -------------
__global__ void score_fin_kernel(const float* __restrict__ ssum,
                                 const float* __restrict__ sroot,
                                 const float* __restrict__ brel,
                                 float* __restrict__ scores,
                                 unsigned long long* __restrict__ key64,
                                 int* __restrict__ iota,
                                 int* __restrict__ newid_init,
                                 float* __restrict__ ozero,
                                 int npg, int n) {
    const int node = blockIdx.x * blockDim.x + threadIdx.x;
    if (node >= n) return;
    const float sc = xla_tanh((ssum[node] + brel[0]) + sroot[node]);
    scores[node] = sc;
    unsigned int u = __float_as_uint(sc);
    unsigned int e = (u & 0x80000000u) ? ~u : (u | 0x80000000u); // ascending encode
    unsigned int kd = ~e;                                         // descending
    const unsigned int g = (unsigned int)(node / npg);
    key64[node] = ((unsigned long long)g << 32) | (unsigned long long)kd;
    iota[node] = node;
    if (newid_init) newid_init[node] = -1;
    if (ozero && node < BGR_ * CC_) ozero[node] = 0.f;
}

// ---------------- selection/gather after sort (1 warp / kept node) -------
__global__ void select_kernel(const float* __restrict__ scores, const int* __restrict__ sidx,
                              const float* __restrict__ xin, float* __restrict__ xout,
                              float* __restrict__ xout2,
                              int* __restrict__ newid, int npg, int k) {
    const int j = blockIdx.x * 8 + (threadIdx.x >> 5);
    if (j >= BGR_ * k) return;
    const int g = j / k, jj = j - g * k;
    const int srcpos = g * npg + jj;
    const int orig = sidx[srcpos];
    const float val = scores[orig];
    const int lane = threadIdx.x & 31;
    float4 v = *(const float4*)(xin + (size_t)orig * CC_ + lane * 4);
    v.x *= val; v.y *= val; v.z *= val; v.w *= val;
    const size_t off = (size_t)j * CC_ + lane * 4;
    *(float4*)(xout + off) = v;
    if (xout2) *(float4*)(xout2 + off) = v;
    if (lane == 0) newid[orig] = j;
}

// ---------------- per-graph mean pooling: parallel partial sums ----------
#define MEAN_BPG 16
__global__ void mean_part_kernel(const float* __restrict__ x, float* __restrict__ out, int k) {
    const int b = blockIdx.x / MEAN_BPG;
    const int chunk = blockIdx.x % MEAN_BPG;
    const int rows = (k + MEAN_BPG - 1) / MEAN_BPG;
    const int r0 = chunk * rows;
    const int r1 = (r0 + rows < k) ? (r0 + rows) : k;
    const int col = threadIdx.x;  // 0..127
    float s = 0.f;
    for (int r = r0; r < r1; ++r)
        s += x[((size_t)b * k + r) * CC_ + col];
    atomicAdd(&out[b * CC_ + col], s);
}

// ---------------- final MLP head (single block) ----------------
__global__ void head_kernel(const float* __restrict__ out1, const float* __restrict__ out2,
                            const float* __restrict__ Wg, const float* __restrict__ bg,
                            const float* __restrict__ Wr1, const float* __restrict__ br1,
                            const float* __restrict__ gg1, const float* __restrict__ be1,
                            const float* __restrict__ Wr2, const float* __restrict__ br2,
                            const float* __restrict__ gg2, const float* __restrict__ be2,
                            const float* __restrict__ Wout, float* __restrict__ out) {
    __shared__ float cat[8][256];
    __shared__ float gmat[8][128];
    __shared__ float r1[8][64];
    __shared__ float r2[8][32];
    const int tid = threadIdx.x;  // 256 threads
    for (int i = tid; i < 8 * 128; i += 256) {
        const int b = i >> 7, c = i & 127;
        cat[b][c]       = out1[i] / (float)KK1_;
        cat[b][c + 128] = out2[i] / (float)KK2_;
    }
    __syncthreads();
    const float inv = 1.0f / sqrtf(1.0f + 1e-5f);
    if (tid < 128) {
        for (int b = 0; b < 8; b++) {
            float s = 0.f;
            for (int k = 0; k < 256; k++) s = fmaf(cat[b][k], Wg[k * 128 + tid], s);
            gmat[b][tid] = s + bg[tid];
        }
    }
    __syncthreads();
    if (tid < 64) {
        for (int b = 0; b < 8; b++) {
            float s = 0.f;
            for (int k = 0; k < 128; k++) s = fmaf(gmat[b][k], Wr1[k * 64 + tid], s);
            s = (s + br1[tid]) * inv * gg1[tid] + be1[tid];
            r1[b][tid] = fmaxf(s, 0.f);
        }
    }
    __syncthreads();
    if (tid < 32) {
        for (int b = 0; b < 8; b++) {
            float s = 0.f;
            for (int k = 0; k < 64; k++) s = fmaf(r1[b][k], Wr2[k * 32 + tid], s);
            s = (s + br2[tid]) * inv * gg2[tid] + be2[tid];
            r2[b][tid] = fmaxf(s, 0.f);
        }
    }
    __syncthreads();
    if (tid < 32) {
        const int b = tid >> 2, j = tid & 3;
        float s = 0.f;
        for (int k = 0; k < 32; k++) s = fmaf(r2[b][k], Wout[k * 4 + j], s);
        out[b * 4 + j] = s;
    }
}

// ---------------- host orchestration ----------------
extern "C" void kernel_launch(void* const* d_in, const int* in_sizes, int n_in,
                              void* d_out, int out_size) {
    const float* x    = (const float*)d_in[0];
    const int*   ei   = (const int*)d_in[1];
    const int*   src  = ei;
    const int*   dst  = ei + EDG_;
    const float* W0   = (const float*)d_in[3];
    const float* b0   = (const float*)d_in[4];
    const float* W1a  = (const float*)d_in[5];
    const float* b1a  = (const float*)d_in[6];
    const float* W1b  = (const float*)d_in[7];
    const float* b1b  = (const float*)d_in[8];
    const float* Wrel1  = (const float*)d_in[9];
    const float* brel1  = (const float*)d_in[10];
    const float* Wroot1 = (const float*)d_in[11];
    const float* W2a  = (const float*)d_in[12];
    const float* b2a  = (const float*)d_in[13];
    const float* W2b  = (const float*)d_in[14];
    const float* b2b  = (const float*)d_in[15];
    const float* Wrel2  = (const float*)d_in[16];
    const float* brel2  = (const float*)d_in[17];
    const float* Wroot2 = (const float*)d_in[18];
    const float* Wg   = (const float*)d_in[19];
    const float* bg   = (const float*)d_in[20];
    const float* Wr1  = (const float*)d_in[21];
    const float* br1  = (const float*)d_in[22];
    const float* gg1  = (const float*)d_in[23];
    const float* be1  = (const float*)d_in[24];
    const float* Wr2  = (const float*)d_in[25];
    const float* br2  = (const float*)d_in[26];
    const float* gg2  = (const float*)d_in[27];
    const float* be2  = (const float*)d_in[28];
    const float* Wout = (const float*)d_in[29];

    float *bufA, *bufB, *bufC, *scores, *srel, *sroot, *ssum, *o1, *o2;
    unsigned long long *key64, *key64B;
    int *iota, *sidx, *newid;
    unsigned char *cubtmp;
    cudaGetSymbolAddress((void**)&bufA, g_bufA);
    cudaGetSymbolAddress((void**)&bufB, g_bufB);
    cudaGetSymbolAddress((void**)&bufC, g_bufC);
    cudaGetSymbolAddress((void**)&scores, g_scores);
    cudaGetSymbolAddress((void**)&srel, g_srel);
    cudaGetSymbolAddress((void**)&sroot, g_sroot);
    cudaGetSymbolAddress((void**)&ssum, g_ssum);
    cudaGetSymbolAddress((void**)&key64, g_key64);
    cudaGetSymbolAddress((void**)&key64B, g_key64B);
    cudaGetSymbolAddress((void**)&iota, g_iota);
    cudaGetSymbolAddress((void**)&sidx, g_sidx);
    cudaGetSymbolAddress((void**)&newid, g_newid);
    cudaGetSymbolAddress((void**)&o1, g_out1);
    cudaGetSymbolAddress((void**)&o2, g_out2);
    cudaGetSymbolAddress((void**)&cubtmp, g_cubtmp);

    cudaFuncSetAttribute(gin_kernel, cudaFuncAttributeMaxDynamicSharedMemorySize, GIN_SMEM);

    const int scat_blocks = (EDG_ + SCAT_EPW * 8 - 1) / (SCAT_EPW * 8);

    // ---- stage 0: h0 = relu(x @ W0 + b0) -> bufA AND bufB (scatter base)
    gemm_kernel<FF_, true, true><<<NB_ / 64, 256>>>(x, W0, b0, bufA, bufB);

    // ---- GIN layer 1: bufB += segsum(h0) ; h1 = gin(bufB), + score dots
    scatter_kernel<<<scat_blocks, 256>>>(bufA, src, dst, nullptr, bufB, EDG_);
    gin_kernel<<<NB_ / 64, 256, GIN_SMEM>>>(bufB, W1a, b1a, W1b, b1b, bufB,
                                            Wrel1, Wroot1, srel, sroot, ssum);  // h1 = bufB

    // ---- SAGPool 1
    scatter_scalar_kernel<<<(EDG_ / 4 + 255) / 256, 256>>>(srel, src, dst, nullptr, ssum, EDG_);
    score_fin_kernel<<<(NB_ + 255) / 256, 256>>>(ssum, sroot, brel1, scores, key64, iota,
                                                 newid, o1, NPG_, NB_);
    {
        size_t tmp = 0;
        cub::DeviceRadixSort::SortPairs(nullptr, tmp, key64, key64B, iota, sidx, NB_, 0, 35);
        if (tmp > sizeof(g_cubtmp)) tmp = sizeof(g_cubtmp);
        cub::DeviceRadixSort::SortPairs((void*)cubtmp, tmp, key64, key64B, iota, sidx, NB_, 0, 35);
    }
    // h2 -> bufC AND bufA (layer-2 scatter base)
    select_kernel<<<NB1_ / 8, 256>>>(scores, sidx, bufB, bufC, bufA, newid, NPG_, KK1_);
    mean_part_kernel<<<BGR_ * MEAN_BPG, 128>>>(bufC, o1, KK1_);

    // ---- GIN layer 2: bufA += segsum(h2, via newid remap) ; h3 = gin(bufA)
    scatter_kernel<<<scat_blocks, 256>>>(bufC, src, dst, newid, bufA, EDG_);
    gin_kernel<<<NB1_ / 64, 256, GIN_SMEM>>>(bufA, W2a, b2a, W2b, b2b, bufC,
                                             Wrel2, Wroot2, srel, sroot, ssum);  // h3 = bufC

    // ---- SAGPool 2
    scatter_scalar_kernel<<<(EDG_ / 4 + 255) / 256, 256>>>(srel, src, dst, newid, ssum, EDG_);
    score_fin_kernel<<<(NB1_ + 255) / 256, 256>>>(ssum, sroot, brel2, scores, key64, iota,
                                                  nullptr, o2, KK1_, NB1_);
    {
        size_t tmp = 0;
        cub::DeviceRadixSort::SortPairs(nullptr, tmp, key64, key64B, iota, sidx, NB1_, 0, 35);
        if (tmp > sizeof(g_cubtmp)) tmp = sizeof(g_cubtmp);
        cub::DeviceRadixSort::SortPairs((void*)cubtmp, tmp, key64, key64B, iota, sidx, NB1_, 0, 35);
    }
    select_kernel<<<NB2_ / 8, 256>>>(scores, sidx, bufC, bufB, nullptr, newid, KK1_, KK2_);
    mean_part_kernel<<<BGR_ * MEAN_BPG, 128>>>(bufB, o2, KK2_);

    // ---- head
    head_kernel<<<1, 256>>>(o1, o2, Wg, bg, Wr1, br1, gg1, be1,
                            Wr2, br2, gg2, be2, Wout, (float*)d_out);
}